// round 2
// baseline (speedup 1.0000x reference)
#include <cuda_runtime.h>
#include <cuda_bf16.h>
#include <cstdint>

// SparseNonzeroAvgPooling: C = 32 channels (fixed by dataset).
//   d_in[0]: in_feats  float32 [N_IN * 32]
//   d_in[1]: in_map    int32   [M]
//   d_in[2]: out_map   int32   [M]
//   d_in[3]: n_out     int32   [1]
//   d_out  : float32   [n_out * 32]
#define CCH 32

// Scratch counts buffer (device global — allocation is forbidden).
// n_out = 250,000; rounded up.
__device__ float g_counts[262144];

// ---------------------------------------------------------------------------
// Kernel 1: zero output accumulator + counts (single grid-stride kernel).
// ---------------------------------------------------------------------------
__global__ void zero_kernel(float4* __restrict__ out4, int n_out4,
                            float* __restrict__ counts, int n_out) {
    int i = blockIdx.x * blockDim.x + threadIdx.x;
    int stride = gridDim.x * blockDim.x;
    for (int j = i; j < n_out4; j += stride)
        out4[j] = make_float4(0.f, 0.f, 0.f, 0.f);
    for (int j = i; j < n_out; j += stride)
        counts[j] = 0.f;
}

// ---------------------------------------------------------------------------
// Kernel 2: scatter-add. 8 threads per (in,out) pair; each thread owns one
// float4 quad of the 32-channel row. red.global.add.v4.f32 issues ONE L2
// reduction transaction for 4 floats (4x fewer atomic issues than scalar).
// Gather side: 8 consecutive threads read one contiguous 128B feature row.
// ---------------------------------------------------------------------------
__global__ void scatter_kernel(const float* __restrict__ feats,
                               const int* __restrict__ in_map,
                               const int* __restrict__ out_map,
                               float* __restrict__ out,
                               float* __restrict__ counts,
                               int M) {
    long long t = (long long)blockIdx.x * blockDim.x + threadIdx.x;
    int p = (int)(t >> 3);
    int q = (int)(t & 7);
    if (p >= M) return;

    int r = __ldg(&in_map[p]);
    int o = __ldg(&out_map[p]);

    const float4 v = __ldg(((const float4*)(feats + (long long)r * CCH)) + q);

    float4* dst = ((float4*)(out + (long long)o * CCH)) + q;
    asm volatile("red.global.add.v4.f32 [%0], {%1, %2, %3, %4};"
                 :: "l"(dst), "f"(v.x), "f"(v.y), "f"(v.z), "f"(v.w)
                 : "memory");

    if (q == 0)
        atomicAdd(&counts[o], 1.0f);
}

// ---------------------------------------------------------------------------
// Kernel 3: out[v] /= max(count[v], 1)
// ---------------------------------------------------------------------------
__global__ void finalize_kernel(float* __restrict__ out,
                                const float* __restrict__ counts,
                                int n_out) {
    int t = blockIdx.x * blockDim.x + threadIdx.x;
    int v = t >> 3;
    int q = t & 7;
    if (v >= n_out) return;

    float scale = 1.0f / fmaxf(counts[v], 1.0f);

    float4* p4 = ((float4*)(out + (long long)v * CCH)) + q;
    float4 s = *p4;
    s.x *= scale; s.y *= scale; s.z *= scale; s.w *= scale;
    *p4 = s;
}

extern "C" void kernel_launch(void* const* d_in, const int* in_sizes, int n_in,
                              void* d_out, int out_size) {
    const float* feats   = (const float*)d_in[0];
    const int*   in_map  = (const int*)d_in[1];
    const int*   out_map = (const int*)d_in[2];
    float*       out     = (float*)d_out;

    int M     = in_sizes[1];
    int n_out = out_size / CCH;

    float* counts = nullptr;
    cudaGetSymbolAddress((void**)&counts, g_counts);

    // 1) zero accumulators
    {
        int n_out4 = out_size / 4;
        zero_kernel<<<2048, 256>>>((float4*)out, n_out4, counts, n_out);
    }

    // 2) scatter-add
    {
        long long total = (long long)M * 8;
        int threads = 256;
        unsigned blocks = (unsigned)((total + threads - 1) / threads);
        scatter_kernel<<<blocks, threads>>>(feats, in_map, out_map,
                                            out, counts, M);
    }

    // 3) finalize (average)
    {
        long long total = (long long)n_out * 8;
        int threads = 256;
        unsigned blocks = (unsigned)((total + threads - 1) / threads);
        finalize_kernel<<<blocks, threads>>>(out, counts, n_out);
    }
}